// round 1
// baseline (speedup 1.0000x reference)
#include <cuda_runtime.h>
#include <math.h>

// KAN linear fused kernel:
//   out[b,o] = sum_i silu(x[b,i]) * scale_base[o,i]
//            + sum_{i,g} Bspline_g(x[b,i]) * coeff[o,i,g] * scale_spline
// Treated as C[M,N] = A[M,K] @ W[K,N] with M=8192, N=1024, K=1024*12,
// where A is generated on the fly (silu + 11 cubic B-spline bases per input).

#define TOKENS  8192
#define IN_DIM  1024
#define OUT_DIM 1024
#define GK      11      // grid_size + spline order
#define NB0     14      // number of order-0 bases (15 knots)
#define NKNOT   15

#define BM 128
#define BN 128
#define IC 8            // input channels per K-chunk
#define BK (IC * 12)    // 96 K-slots per chunk
#define NTHREADS 256

#define SMEM_FLOATS (BK * BM + BK * BN)
#define SMEM_BYTES  (SMEM_FLOATS * 4)

__global__ void __launch_bounds__(NTHREADS, 2)
kan_fused_kernel(const float* __restrict__ x,
                 const float* __restrict__ grid,
                 const float* __restrict__ coeff,
                 const float* __restrict__ scale_base,
                 const float* __restrict__ scale_spline,
                 float* __restrict__ out)
{
    extern __shared__ float smem[];
    float (*As)[BM] = (float (*)[BM])smem;                 // [BK][BM]
    float (*Ws)[BN] = (float (*)[BN])(smem + BK * BM);     // [BK][BN]

    const float ss = scale_spline[0];

    const int m0 = blockIdx.y * BM;
    const int n0 = blockIdx.x * BN;
    const int tid = threadIdx.x;
    const int tx = tid & 15;   // output-col group: cols tx*8 .. tx*8+7
    const int ty = tid >> 4;   // token-row group:  rows ty*8 .. ty*8+7

    float acc[8][8];
    #pragma unroll
    for (int a = 0; a < 8; a++)
        #pragma unroll
        for (int b = 0; b < 8; b++) acc[a][b] = 0.0f;

    for (int i0 = 0; i0 < IN_DIM; i0 += IC) {
        // ------------------------------------------------------------------
        // Phase 1: generate A features into smem.
        // 1024 (token, input) pairs; each thread handles 4 with one float4 x load.
        // ------------------------------------------------------------------
        {
            const int p  = tid * 4;
            const int bl = p >> 3;        // local token 0..127
            const int il = p & 7;         // 0 or 4
            const float4 xv = *(const float4*)(x + (size_t)(m0 + bl) * IN_DIM + i0 + il);
            float xs[4] = {xv.x, xv.y, xv.z, xv.w};

            #pragma unroll
            for (int r = 0; r < 4; r++) {
                const int ii = i0 + il + r;
                const float xx = xs[r];

                // silu(x) = x * sigmoid(x)
                const float sil = xx / (1.0f + __expf(-xx));

                // knots for this input channel
                float g[NKNOT];
                #pragma unroll
                for (int j = 0; j < NKNOT; j++)
                    g[j] = __ldg(grid + (size_t)ii * NKNOT + j);

                // order-0 indicator bases
                float bas[NB0];
                #pragma unroll
                for (int j = 0; j < NB0; j++)
                    bas[j] = (xx >= g[j] && xx < g[j + 1]) ? 1.0f : 0.0f;

                // Cox-de Boor recursion to order 3
                #pragma unroll
                for (int kk = 1; kk <= 3; kk++) {
                    #pragma unroll
                    for (int j = 0; j < NB0 - 1; j++) {
                        if (j < NB0 - kk) {
                            float left  = (xx - g[j])        / (g[j + kk]     - g[j]);
                            float right = (g[j + kk + 1] - xx) / (g[j + kk + 1] - g[j + 1]);
                            bas[j] = left * bas[j] + right * bas[j + 1];
                        }
                    }
                }

                const int kbase = (il + r) * 12;
                As[kbase][bl] = sil;
                #pragma unroll
                for (int j = 0; j < GK; j++)
                    As[kbase + 1 + j][bl] = bas[j];
            }
        }

        // ------------------------------------------------------------------
        // Phase 2: load W tile into smem (scale_base into slot 0, coeff*ss 1..11).
        // 1024 (output, input) pairs; each thread handles 4.
        // ------------------------------------------------------------------
        {
            const int p  = tid * 4;
            const int ol = p >> 3;        // local output 0..127
            const int il = p & 7;         // 0 or 4
            const int o  = n0 + ol;

            #pragma unroll
            for (int r = 0; r < 4; r++) {
                const int ii = i0 + il + r;
                const int kbase = (il + r) * 12;
                Ws[kbase][ol] = __ldg(scale_base + (size_t)o * IN_DIM + ii);
                const float* cr = coeff + ((size_t)o * IN_DIM + ii) * GK;
                #pragma unroll
                for (int j = 0; j < GK; j++)
                    Ws[kbase + 1 + j][ol] = __ldg(cr + j) * ss;
            }
        }

        __syncthreads();

        // ------------------------------------------------------------------
        // Phase 3: 8x8 register-tile FMA over BK=96 K-slots
        // ------------------------------------------------------------------
        #pragma unroll 4
        for (int k = 0; k < BK; k++) {
            float a[8], w[8];
            *(float4*)&a[0] = *(const float4*)&As[k][ty * 8];
            *(float4*)&a[4] = *(const float4*)&As[k][ty * 8 + 4];
            *(float4*)&w[0] = *(const float4*)&Ws[k][tx * 8];
            *(float4*)&w[4] = *(const float4*)&Ws[k][tx * 8 + 4];
            #pragma unroll
            for (int mi = 0; mi < 8; mi++)
                #pragma unroll
                for (int ni = 0; ni < 8; ni++)
                    acc[mi][ni] = fmaf(a[mi], w[ni], acc[mi][ni]);
        }

        __syncthreads();
    }

    // ----------------------------------------------------------------------
    // Epilogue: write 8x8 tile
    // ----------------------------------------------------------------------
    #pragma unroll
    for (int mi = 0; mi < 8; mi++) {
        const int m = m0 + ty * 8 + mi;
        float* op = out + (size_t)m * OUT_DIM + n0 + tx * 8;
        float4 v0 = make_float4(acc[mi][0], acc[mi][1], acc[mi][2], acc[mi][3]);
        float4 v1 = make_float4(acc[mi][4], acc[mi][5], acc[mi][6], acc[mi][7]);
        *(float4*)op       = v0;
        *(float4*)(op + 4) = v1;
    }
}

extern "C" void kernel_launch(void* const* d_in, const int* in_sizes, int n_in,
                              void* d_out, int out_size)
{
    const float* x           = (const float*)d_in[0];
    const float* grid        = (const float*)d_in[1];
    const float* coeff       = (const float*)d_in[2];
    const float* scale_base  = (const float*)d_in[3];
    const float* scale_spl   = (const float*)d_in[4];
    float* out               = (float*)d_out;

    static bool attr_set = false;
    if (!attr_set) {
        cudaFuncSetAttribute(kan_fused_kernel,
                             cudaFuncAttributeMaxDynamicSharedMemorySize,
                             SMEM_BYTES);
        attr_set = true;
    }

    dim3 grid_dim(OUT_DIM / BN, TOKENS / BM);   // (8, 64)
    kan_fused_kernel<<<grid_dim, NTHREADS, SMEM_BYTES>>>(
        x, grid, coeff, scale_base, scale_spl, out);
}